// round 1
// baseline (speedup 1.0000x reference)
#include <cuda_runtime.h>
#include <math.h>

// ---------------- problem constants ----------------
#define Bb 2
#define Cc 384
#define Hh 32
#define Ww 32
#define HW 1024
#define NHEAD 12
#define NGROUP 6
#define HC 32
#define GC 64
#define BG (Bb*NGROUP)      // 12
#define BH (Bb*NHEAD)       // 24
#define NS 1024             // n_sample
#define SCALE 0.17677669529663687f  // 32^-0.5

#define NBUF (Bb*Cc*HW)     // 786432

// ---------------- scratch (no cudaMalloc allowed) ----------------
__device__ float g_q [NBUF];
__device__ float g_xs[NBUF];
__device__ float g_k [NBUF];
__device__ float g_v [NBUF];
__device__ float g_o [NBUF];
__device__ float2 g_pos[BG*NS];

// ---------------- generic channel GEMM: Y[b,o,n] = sum_c W[o,c] X[b,c,n] + bias[o]
// M=384, K=384, N=1024. Tiles 64x64x16, 256 threads, 4x4 per thread.
__global__ __launch_bounds__(256) void gemm384(
    const float* __restrict__ W, const float* __restrict__ bias,
    const float* __restrict__ X, float* __restrict__ Y)
{
    const int K = 384, N = 1024;
    int n0 = blockIdx.x * 64, m0 = blockIdx.y * 64, b = blockIdx.z;
    X += (size_t)b * K * N;
    Y += (size_t)b * 384 * N;

    __shared__ float As[16][64];
    __shared__ float Bs[16][64];

    int tid = threadIdx.x;
    int tx = tid & 15, ty = tid >> 4;
    float acc[4][4] = {};

    for (int k0 = 0; k0 < K; k0 += 16) {
        { // A tile: As[k][m] = W[(m0+m)*K + k0+k]
            int ma = tid >> 2, kq = (tid & 3) * 4;
            float4 fa = *(const float4*)(W + (m0 + ma) * K + k0 + kq);
            As[kq + 0][ma] = fa.x;
            As[kq + 1][ma] = fa.y;
            As[kq + 2][ma] = fa.z;
            As[kq + 3][ma] = fa.w;
        }
        { // B tile: Bs[k][n] = X[(k0+k)*N + n0+n]
            int kb = tid >> 4, nq = (tid & 15) * 4;
            *(float4*)&Bs[kb][nq] = *(const float4*)(X + (k0 + kb) * N + n0 + nq);
        }
        __syncthreads();
        #pragma unroll
        for (int kk = 0; kk < 16; kk++) {
            float4 a  = *(const float4*)&As[kk][ty * 4];
            float4 b4 = *(const float4*)&Bs[kk][tx * 4];
            float av[4] = {a.x, a.y, a.z, a.w};
            float bv[4] = {b4.x, b4.y, b4.z, b4.w};
            #pragma unroll
            for (int i = 0; i < 4; i++)
                #pragma unroll
                for (int j = 0; j < 4; j++)
                    acc[i][j] += av[i] * bv[j];
        }
        __syncthreads();
    }
    #pragma unroll
    for (int i = 0; i < 4; i++) {
        int o = m0 + ty * 4 + i;
        float bi = bias[o];
        #pragma unroll
        for (int j = 0; j < 4; j++)
            Y[o * N + n0 + tx * 4 + j] = acc[i][j] + bi;
    }
}

// ---------------- offset branch: depthwise7x7 -> LN(ch) -> GELU -> 1x1(2) -> tanh -> pos
// one block per (bg, pixel), 64 threads = 64 group channels
__global__ __launch_bounds__(64) void conv_offset_kernel(
    const float* __restrict__ q, const float* __restrict__ dw_w,
    const float* __restrict__ dw_b, const float* __restrict__ ln_g,
    const float* __restrict__ ln_b, const float* __restrict__ pw_w,
    float2* __restrict__ pos)
{
    int bg  = blockIdx.x >> 10;
    int pix = blockIdx.x & 1023;
    int ch  = threadIdx.x;
    int py = pix >> 5, px = pix & 31;

    const float* qp = q + (size_t)(bg * 64 + ch) * 1024;
    float acc = dw_b[ch];
    #pragma unroll
    for (int ky = 0; ky < 7; ky++) {
        int iy = py + ky - 3;
        if (iy < 0 || iy > 31) continue;
        #pragma unroll
        for (int kx = 0; kx < 7; kx++) {
            int ix = px + kx - 3;
            if (ix < 0 || ix > 31) continue;
            acc += dw_w[ch * 49 + ky * 7 + kx] * qp[iy * 32 + ix];
        }
    }

    __shared__ float buf0[64];
    __shared__ float buf1[64];
    __shared__ float stats[2];

    buf0[ch] = acc;
    __syncthreads();
    if (ch == 0) {
        float s = 0.f;
        for (int i = 0; i < 64; i++) s += buf0[i];
        stats[0] = s * (1.f / 64.f);
    }
    __syncthreads();
    float mu = stats[0];
    float d = acc - mu;
    buf0[ch] = d * d;
    __syncthreads();
    if (ch == 0) {
        float s = 0.f;
        for (int i = 0; i < 64; i++) s += buf0[i];
        stats[1] = s * (1.f / 64.f);
    }
    __syncthreads();
    float var = stats[1];
    float o = d * rsqrtf(var + 1e-5f) * ln_g[ch] + ln_b[ch];
    // exact GELU
    o = 0.5f * o * (1.f + erff(o * 0.70710678118654752f));

    buf0[ch] = o * pw_w[ch];        // row 0 -> y offset
    buf1[ch] = o * pw_w[64 + ch];   // row 1 -> x offset
    __syncthreads();
    if (ch == 0) {
        float sy = 0.f, sx = 0.f;
        for (int i = 0; i < 64; i++) { sy += buf0[i]; sx += buf1[i]; }
        float offy = tanhf(sy) * 0.0625f;   // (1/32)*2
        float offx = tanhf(sx) * 0.0625f;
        float refy = ((py + 0.5f) * (1.f / 32.f)) * 2.f - 1.f;
        float refx = ((px + 0.5f) * (1.f / 32.f)) * 2.f - 1.f;
        pos[bg * 1024 + pix] = make_float2(offx + refx, offy + refy); // (x, y)
    }
}

// ---------------- grid sample x at pos -> x_s  (align_corners=True, zeros pad)
__global__ __launch_bounds__(256) void sample_kernel(
    const float* __restrict__ x, const float2* __restrict__ pos,
    float* __restrict__ xs)
{
    int idx = blockIdx.x * 256 + threadIdx.x;   // (bg*64+ch)*1024 + s
    int s  = idx & 1023;
    int bg = idx >> 16;
    float2 p = pos[bg * 1024 + s];
    float gx = (p.x + 1.f) * 0.5f * 31.f;
    float gy = (p.y + 1.f) * 0.5f * 31.f;
    float x0f = floorf(gx), y0f = floorf(gy);
    float wx = gx - x0f, wy = gy - y0f;
    int x0 = (int)x0f, y0 = (int)y0f;

    const float* xp = x + (size_t)(idx >> 10) * 1024;   // (bg*64+ch) plane
    float r = 0.f;
    bool vx0 = (x0 >= 0) & (x0 <= 31), vx1 = (x0 >= -1) & (x0 <= 30);
    bool vy0 = (y0 >= 0) & (y0 <= 31), vy1 = (y0 >= -1) & (y0 <= 30);
    if (vx0 && vy0) r += (1.f - wx) * (1.f - wy) * xp[y0 * 32 + x0];
    if (vx1 && vy0) r += wx * (1.f - wy) * xp[y0 * 32 + x0 + 1];
    if (vx0 && vy1) r += (1.f - wx) * wy * xp[(y0 + 1) * 32 + x0];
    if (vx1 && vy1) r += wx * wy * xp[(y0 + 1) * 32 + x0 + 1];
    xs[idx] = r;
}

// ---------------- fused attention: scores(K=32) + RPE bilinear + softmax + PV(K=1024)
// block: 256 threads, handles one bh and 8 query rows (m0..m0+7), all 1024 keys.
__global__ __launch_bounds__(256) void attn_kernel(
    const float* __restrict__ q, const float* __restrict__ k,
    const float* __restrict__ v, const float2* __restrict__ pos,
    const float* __restrict__ rpe, float* __restrict__ out)
{
    extern __shared__ float sm[];
    float* p_s  = sm;                 // 8*1024
    float* v_s  = sm + 8192;          // 256*33
    float* q_s  = sm + 8192 + 8448;   // 256
    float* redA = q_s + 256;          // 8
    float* redB = redA + 8;           // 8

    int bh = blockIdx.y;
    int m0 = blockIdx.x * 8;
    int b = bh / 12, head = bh % 12;
    int bg = b * 6 + (head >> 1);
    int tid = threadIdx.x;
    int lane = tid & 31, warp = tid >> 5;

    { // load 8x32 q tile, scale folded
        int r = tid >> 5, c = tid & 31;
        q_s[tid] = q[(size_t)(bh * 32 + c) * 1024 + m0 + r] * SCALE;
    }
    __syncthreads();

    float acc[8][4];
    #pragma unroll
    for (int r = 0; r < 8; r++)
        #pragma unroll
        for (int j = 0; j < 4; j++) acc[r][j] = 0.f;

    // ---- scores: q · k over 32 channels; n = jn*256 + tid
    const float* kb = k + (size_t)bh * 32 * 1024;
    #pragma unroll 4
    for (int c = 0; c < 32; c++) {
        float kc0 = kb[c * 1024 + tid];
        float kc1 = kb[c * 1024 + 256 + tid];
        float kc2 = kb[c * 1024 + 512 + tid];
        float kc3 = kb[c * 1024 + 768 + tid];
        #pragma unroll
        for (int r = 0; r < 8; r++) {
            float qv = q_s[r * 32 + c];
            acc[r][0] += qv * kc0;
            acc[r][1] += qv * kc1;
            acc[r][2] += qv * kc2;
            acc[r][3] += qv * kc3;
        }
    }

    // ---- RPE bilinear bias on 63x63 table
    const float* T = rpe + head * 63 * 63;
    float pxv[4], pyv[4];
    #pragma unroll
    for (int jn = 0; jn < 4; jn++) {
        float2 p = pos[bg * 1024 + jn * 256 + tid];
        pxv[jn] = p.x; pyv[jn] = p.y;
    }
    #pragma unroll
    for (int r = 0; r < 8; r++) {
        int m = m0 + r;
        float qy = (((m >> 5) + 0.5f) * (1.f / 32.f)) * 2.f - 1.f;
        float qx = (((m & 31) + 0.5f) * (1.f / 32.f)) * 2.f - 1.f;
        #pragma unroll
        for (int jn = 0; jn < 4; jn++) {
            float dx = (qx - pxv[jn]) * 0.5f;
            float dy = (qy - pyv[jn]) * 0.5f;
            float gx = (dx + 1.f) * 31.f;   // 0.5*(63-1)
            float gy = (dy + 1.f) * 31.f;
            float x0f = floorf(gx), y0f = floorf(gy);
            float wx = gx - x0f, wy = gy - y0f;
            int x0 = (int)x0f, y0 = (int)y0f;
            float bias = 0.f;
            bool vx0 = (x0 >= 0) & (x0 <= 62), vx1 = (x0 >= -1) & (x0 <= 61);
            bool vy0 = (y0 >= 0) & (y0 <= 62), vy1 = (y0 >= -1) & (y0 <= 61);
            if (vx0 && vy0) bias += (1.f - wx) * (1.f - wy) * T[y0 * 63 + x0];
            if (vx1 && vy0) bias += wx * (1.f - wy) * T[y0 * 63 + x0 + 1];
            if (vx0 && vy1) bias += (1.f - wx) * wy * T[(y0 + 1) * 63 + x0];
            if (vx1 && vy1) bias += wx * wy * T[(y0 + 1) * 63 + x0 + 1];
            acc[r][jn] += bias;
        }
    }

    // ---- softmax per row r over 1024 keys
    #pragma unroll 1
    for (int r = 0; r < 8; r++) {
        float mx = fmaxf(fmaxf(acc[r][0], acc[r][1]), fmaxf(acc[r][2], acc[r][3]));
        #pragma unroll
        for (int o = 16; o > 0; o >>= 1) mx = fmaxf(mx, __shfl_xor_sync(0xffffffffu, mx, o));
        if (lane == 0) redA[warp] = mx;
        __syncthreads();
        float rmax = redA[0];
        #pragma unroll
        for (int w = 1; w < 8; w++) rmax = fmaxf(rmax, redA[w]);
        float s = 0.f;
        #pragma unroll
        for (int j = 0; j < 4; j++) {
            acc[r][j] = __expf(acc[r][j] - rmax);
            s += acc[r][j];
        }
        #pragma unroll
        for (int o = 16; o > 0; o >>= 1) s += __shfl_xor_sync(0xffffffffu, s, o);
        __syncthreads();
        if (lane == 0) redB[warp] = s;
        __syncthreads();
        float rsum = 0.f;
        #pragma unroll
        for (int w = 0; w < 8; w++) rsum += redB[w];
        float inv = 1.f / rsum;
        #pragma unroll
        for (int j = 0; j < 4; j++)
            p_s[r * 1024 + j * 256 + tid] = acc[r][j] * inv;
    }
    __syncthreads();

    // ---- PV: out[c, m0+r] = sum_n p[r][n] * v[c][n]
    int c = tid & 31, r = tid >> 5;
    const float* vb = v + (size_t)bh * 32 * 1024;
    float o_acc = 0.f;
    for (int nc = 0; nc < 4; nc++) {
        // stage v chunk [n=256][c=32] into smem, pad 33
        #pragma unroll 8
        for (int ccc = 0; ccc < 32; ccc++)
            v_s[tid * 33 + ccc] = vb[ccc * 1024 + nc * 256 + tid];
        __syncthreads();
        const float* pr = p_s + r * 1024 + nc * 256;
        #pragma unroll 8
        for (int nn = 0; nn < 256; nn += 4) {
            float4 pv = *(const float4*)(pr + nn);
            o_acc += pv.x * v_s[(nn + 0) * 33 + c];
            o_acc += pv.y * v_s[(nn + 1) * 33 + c];
            o_acc += pv.z * v_s[(nn + 2) * 33 + c];
            o_acc += pv.w * v_s[(nn + 3) * 33 + c];
        }
        __syncthreads();
    }
    out[(size_t)(bh * 32 + c) * 1024 + m0 + r] = o_acc;
}

// ---------------- launch ----------------
extern "C" void kernel_launch(void* const* d_in, const int* in_sizes, int n_in,
                              void* d_out, int out_size)
{
    const float* x    = (const float*)d_in[0];
    const float* Wq   = (const float*)d_in[1];
    const float* bq   = (const float*)d_in[2];
    const float* Wk   = (const float*)d_in[3];
    const float* bk   = (const float*)d_in[4];
    const float* Wv   = (const float*)d_in[5];
    const float* bv   = (const float*)d_in[6];
    const float* Wo   = (const float*)d_in[7];
    const float* bo   = (const float*)d_in[8];
    const float* dw_w = (const float*)d_in[9];
    const float* dw_b = (const float*)d_in[10];
    const float* ln_g = (const float*)d_in[11];
    const float* ln_b = (const float*)d_in[12];
    const float* pw_w = (const float*)d_in[13];
    const float* rpe  = (const float*)d_in[14];

    float *q, *xs, *k, *v, *ob;
    float2* pos;
    cudaGetSymbolAddress((void**)&q,   g_q);
    cudaGetSymbolAddress((void**)&xs,  g_xs);
    cudaGetSymbolAddress((void**)&k,   g_k);
    cudaGetSymbolAddress((void**)&v,   g_v);
    cudaGetSymbolAddress((void**)&ob,  g_o);
    cudaGetSymbolAddress((void**)&pos, g_pos);

    dim3 gg(16, 6, 2);
    gemm384<<<gg, 256>>>(Wq, bq, x, q);
    conv_offset_kernel<<<BG * HW, 64>>>(q, dw_w, dw_b, ln_g, ln_b, pw_w, pos);
    sample_kernel<<<(BG * GC * NS) / 256, 256>>>(x, pos, xs);
    gemm384<<<gg, 256>>>(Wk, bk, xs, k);
    gemm384<<<gg, 256>>>(Wv, bv, xs, v);

    const int SMEM = (8192 + 8448 + 256 + 16) * 4; // 67648 B
    cudaFuncSetAttribute(attn_kernel, cudaFuncAttributeMaxDynamicSharedMemorySize, SMEM);
    attn_kernel<<<dim3(128, 24), 256, SMEM>>>(q, k, v, pos, rpe, ob);

    gemm384<<<gg, 256>>>(Wo, bo, ob, (float*)d_out);
}

// round 2
// speedup vs baseline: 1.8092x; 1.8092x over previous
#include <cuda_runtime.h>
#include <math.h>

// ---------------- problem constants ----------------
#define Bb 2
#define Cc 384
#define HW 1024
#define NHEAD 12
#define NGROUP 6
#define BG (Bb*NGROUP)      // 12
#define BH (Bb*NHEAD)       // 24
#define NS 1024
#define SCALE 0.17677669529663687f

#define NBUF (Bb*Cc*HW)     // 786432

// ---------------- scratch ----------------
__device__ float g_q [NBUF];
__device__ float g_xs[NBUF];
__device__ float g_k [NBUF];
__device__ float g_v [NBUF];
__device__ float g_o [NBUF];
__device__ float2 g_pos[BG*NS];

// =======================================================================
// GEMM: Y[b,o,n] = sum_c W[o,c] X[b,c,n] + bias[o]; M=384,K=384,N=1024
// 64x64 tile, double-buffered smem, 1 sync per K-chunk.
// =======================================================================
__device__ __forceinline__ void gemm_body(
    const float* __restrict__ W, const float* __restrict__ bias,
    const float* __restrict__ X, float* __restrict__ Y,
    int m0, int n0)
{
    const int K = 384, N = 1024;
    __shared__ float As[2][64*20];   // [m][k] pad 20
    __shared__ float Bs[2][16*68];   // [k][n] pad 68

    int tid = threadIdx.x;
    int tx = tid & 15, ty = tid >> 4;
    int ma = tid >> 2, kq = (tid & 3) * 4;
    int kb = tid >> 4, nq = (tid & 15) * 4;

    float4 fa = *(const float4*)(W + (m0 + ma) * K + kq);
    float4 fb = *(const float4*)(X + kb * N + n0 + nq);

    float acc[4][4] = {};
    int buf = 0;
    #pragma unroll 1
    for (int k0 = 0; k0 < K; k0 += 16) {
        *(float4*)&As[buf][ma*20 + kq] = fa;
        *(float4*)&Bs[buf][kb*68 + nq] = fb;
        __syncthreads();
        if (k0 + 16 < K) {
            fa = *(const float4*)(W + (m0 + ma) * K + k0 + 16 + kq);
            fb = *(const float4*)(X + (size_t)(k0 + 16 + kb) * N + n0 + nq);
        }
        #pragma unroll
        for (int kk = 0; kk < 16; kk++) {
            float4 b4 = *(const float4*)&Bs[buf][kk*68 + tx*4];
            float a0 = As[buf][(ty*4+0)*20 + kk];
            float a1 = As[buf][(ty*4+1)*20 + kk];
            float a2 = As[buf][(ty*4+2)*20 + kk];
            float a3 = As[buf][(ty*4+3)*20 + kk];
            acc[0][0] = fmaf(a0, b4.x, acc[0][0]); acc[0][1] = fmaf(a0, b4.y, acc[0][1]);
            acc[0][2] = fmaf(a0, b4.z, acc[0][2]); acc[0][3] = fmaf(a0, b4.w, acc[0][3]);
            acc[1][0] = fmaf(a1, b4.x, acc[1][0]); acc[1][1] = fmaf(a1, b4.y, acc[1][1]);
            acc[1][2] = fmaf(a1, b4.z, acc[1][2]); acc[1][3] = fmaf(a1, b4.w, acc[1][3]);
            acc[2][0] = fmaf(a2, b4.x, acc[2][0]); acc[2][1] = fmaf(a2, b4.y, acc[2][1]);
            acc[2][2] = fmaf(a2, b4.z, acc[2][2]); acc[2][3] = fmaf(a2, b4.w, acc[2][3]);
            acc[3][0] = fmaf(a3, b4.x, acc[3][0]); acc[3][1] = fmaf(a3, b4.y, acc[3][1]);
            acc[3][2] = fmaf(a3, b4.z, acc[3][2]); acc[3][3] = fmaf(a3, b4.w, acc[3][3]);
        }
        buf ^= 1;
    }
    #pragma unroll
    for (int i = 0; i < 4; i++) {
        int o = m0 + ty * 4 + i;
        float bi = bias[o];
        #pragma unroll
        for (int j = 0; j < 4; j++)
            Y[o * N + n0 + tx * 4 + j] = acc[i][j] + bi;
    }
}

__global__ __launch_bounds__(256) void gemm384(
    const float* __restrict__ W, const float* __restrict__ bias,
    const float* __restrict__ X, float* __restrict__ Y)
{
    int b = blockIdx.z;
    gemm_body(W, bias, X + (size_t)b*384*1024, Y + (size_t)b*384*1024,
              blockIdx.y*64, blockIdx.x*64);
}

// fused K and V gemms (independent -> run concurrently in one launch)
__global__ __launch_bounds__(256) void gemm384_kv(
    const float* __restrict__ Wk, const float* __restrict__ bk,
    const float* __restrict__ Wv, const float* __restrict__ bv,
    const float* __restrict__ X, float* __restrict__ Yk, float* __restrict__ Yv)
{
    int b = blockIdx.z;
    int sel = blockIdx.y >= 6;
    int m0 = (blockIdx.y - sel*6) * 64;
    const float* W = sel ? Wv : Wk;
    const float* bias = sel ? bv : bk;
    float* Y = sel ? Yv : Yk;
    gemm_body(W, bias, X + (size_t)b*384*1024, Y + (size_t)b*384*1024,
              m0, blockIdx.x*64);
}

// =======================================================================
// depthwise 7x7 conv: block = one (bg,ch) plane, smem-tiled, coalesced
// =======================================================================
__global__ __launch_bounds__(256) void dwconv_kernel(
    const float* __restrict__ q, const float* __restrict__ dw_w,
    const float* __restrict__ dw_b, float* __restrict__ tmp)
{
    int plane = blockIdx.x;            // bg*64 + ch
    int ch = plane & 63;
    __shared__ float s[1024];
    __shared__ float w[49];
    const float* qp = q + (size_t)plane * 1024;
    int tid = threadIdx.x;
    *(float4*)&s[tid*4] = *(const float4*)(qp + tid*4);
    if (tid < 49) w[tid] = dw_w[ch*49 + tid];
    float bch = dw_b[ch];
    __syncthreads();
    #pragma unroll
    for (int pp = 0; pp < 4; pp++) {
        int pix = tid + pp*256;
        int py = pix >> 5, px = pix & 31;
        float a = bch;
        #pragma unroll
        for (int ky = 0; ky < 7; ky++) {
            int iy = py + ky - 3;
            if (iy < 0 || iy > 31) continue;
            #pragma unroll
            for (int kx = 0; kx < 7; kx++) {
                int ix = px + kx - 3;
                if (ix < 0 || ix > 31) continue;
                a += w[ky*7+kx] * s[iy*32+ix];
            }
        }
        tmp[(size_t)plane*1024 + pix] = a;
    }
}

// =======================================================================
// LN(ch) + GELU + 1x1(2ch) + tanh -> pos.  block = 128 pixels of one bg.
// thread: (pixel, half) half covers 32 channels.
// =======================================================================
__global__ __launch_bounds__(256) void offs_kernel(
    const float* __restrict__ tmp, const float* __restrict__ ln_g,
    const float* __restrict__ ln_b, const float* __restrict__ pw_w,
    float2* __restrict__ pos)
{
    int bg = blockIdx.x >> 3;
    int p0 = (blockIdx.x & 7) * 128;
    int tid = threadIdx.x;
    int pl = tid & 127, half = tid >> 7;
    int pix = p0 + pl;
    const float* tp = tmp + (size_t)bg*65536 + (size_t)half*32768 + pix;

    __shared__ float red[256], red2[256], mu_s[128], rs_s[128];

    float vals[32];
    float s1 = 0.f;
    #pragma unroll
    for (int i = 0; i < 32; i++) { vals[i] = tp[i*1024]; s1 += vals[i]; }
    red[tid] = s1;
    __syncthreads();
    if (half == 0) mu_s[pl] = (red[pl] + red[pl+128]) * (1.f/64.f);
    __syncthreads();
    float mu = mu_s[pl];
    float s2 = 0.f;
    #pragma unroll
    for (int i = 0; i < 32; i++) { float d = vals[i]-mu; s2 += d*d; }
    red[tid] = s2;
    __syncthreads();
    if (half == 0) rs_s[pl] = rsqrtf((red[pl]+red[pl+128])*(1.f/64.f) + 1e-5f);
    __syncthreads();
    float rs = rs_s[pl];
    float sy = 0.f, sx = 0.f;
    #pragma unroll
    for (int i = 0; i < 32; i++) {
        int ch = half*32 + i;
        float o = (vals[i]-mu)*rs*ln_g[ch] + ln_b[ch];
        o = 0.5f*o*(1.f + erff(o*0.70710678118654752f));
        sy += o * pw_w[ch];
        sx += o * pw_w[64+ch];
    }
    red[tid] = sy; red2[tid] = sx;
    __syncthreads();
    if (half == 0) {
        float oy = tanhf(red[pl]+red[pl+128]) * 0.0625f;
        float ox = tanhf(red2[pl]+red2[pl+128]) * 0.0625f;
        int py = pix >> 5, px = pix & 31;
        float refy = ((py + 0.5f)*(1.f/16.f)) - 1.f;
        float refx = ((px + 0.5f)*(1.f/16.f)) - 1.f;
        pos[bg*1024 + pix] = make_float2(ox + refx, oy + refy); // (x,y)
    }
}

// =======================================================================
// grid sample x at pos -> x_s
// =======================================================================
__global__ __launch_bounds__(256) void sample_kernel(
    const float* __restrict__ x, const float2* __restrict__ pos,
    float* __restrict__ xs)
{
    int idx = blockIdx.x * 256 + threadIdx.x;
    int s  = idx & 1023;
    int bg = idx >> 16;
    float2 p = pos[bg * 1024 + s];
    float gx = (p.x + 1.f) * 0.5f * 31.f;
    float gy = (p.y + 1.f) * 0.5f * 31.f;
    float x0f = floorf(gx), y0f = floorf(gy);
    float wx = gx - x0f, wy = gy - y0f;
    int x0 = (int)x0f, y0 = (int)y0f;
    const float* xp = x + (size_t)(idx >> 10) * 1024;
    float r = 0.f;
    bool vx0 = (x0 >= 0) & (x0 <= 31), vx1 = (x0 >= -1) & (x0 <= 30);
    bool vy0 = (y0 >= 0) & (y0 <= 31), vy1 = (y0 >= -1) & (y0 <= 30);
    if (vx0 && vy0) r += (1.f - wx) * (1.f - wy) * xp[y0 * 32 + x0];
    if (vx1 && vy0) r += wx * (1.f - wy) * xp[y0 * 32 + x0 + 1];
    if (vx0 && vy1) r += (1.f - wx) * wy * xp[(y0 + 1) * 32 + x0];
    if (vx1 && vy1) r += wx * wy * xp[(y0 + 1) * 32 + x0 + 1];
    xs[idx] = r;
}

// =======================================================================
// fused attention, M=16 query rows per block.
// smem layout (floats): p[1024*20] | v[128*36] | q[512] | redw[128] | fin[32]
// =======================================================================
#define P_STRIDE 20
#define V_STRIDE 36
__global__ __launch_bounds__(256, 2) void attn_kernel(
    const float* __restrict__ qg, const float* __restrict__ kg,
    const float* __restrict__ vg, const float2* __restrict__ pos,
    const float* __restrict__ rpe, float* __restrict__ out)
{
    extern __shared__ float sm[];
    float* p_s  = sm;                       // 20480
    float* v_s  = sm + 20480;               // 4608
    float* q_s  = sm + 20480 + 4608;        // 512  [c*16 + r]
    float* redw = q_s + 512;                // 128  [r*8 + warp]
    float* fin  = redw + 128;               // 32   [0..15]=max [16..31]=inv

    int bh = blockIdx.y;
    int m0 = blockIdx.x * 16;
    int head = bh % 12;
    int bg = (bh / 12) * 6 + (head >> 1);
    int tid = threadIdx.x;
    int lane = tid & 31, warp = tid >> 5;

    // load q tile [32c][16r], scale folded
    #pragma unroll
    for (int i = tid; i < 512; i += 256) {
        int c = i >> 4, r = i & 15;
        q_s[i] = qg[(size_t)(bh*32 + c)*1024 + m0 + r] * SCALE;
    }
    __syncthreads();

    // ---- scores: acc[r][j], n = tid + 256*j
    float acc[16][4] = {};
    const float* kb = kg + (size_t)bh * 32768;
    #pragma unroll 4
    for (int c = 0; c < 32; c++) {
        float k0 = kb[c*1024 + tid];
        float k1 = kb[c*1024 + tid + 256];
        float k2 = kb[c*1024 + tid + 512];
        float k3 = kb[c*1024 + tid + 768];
        #pragma unroll
        for (int r = 0; r < 16; r++) {
            float qv = q_s[c*16 + r];
            acc[r][0] = fmaf(qv, k0, acc[r][0]);
            acc[r][1] = fmaf(qv, k1, acc[r][1]);
            acc[r][2] = fmaf(qv, k2, acc[r][2]);
            acc[r][3] = fmaf(qv, k3, acc[r][3]);
        }
    }

    // ---- RPE bilinear bias (y constant over the 16 rows of this block)
    {
        const float* T = rpe + head * 3969;
        int yq = m0 >> 5, xb = m0 & 31;
        float qy  = (yq + 0.5f) * (1.f/16.f) - 1.f;
        float qx0 = (xb + 0.5f) * (1.f/16.f) - 1.f;
        #pragma unroll
        for (int j = 0; j < 4; j++) {
            float2 p = pos[bg*1024 + tid + 256*j];
            float gy = fmaf(qy - p.y, 15.5f, 31.f);
            float y0f = floorf(gy);
            float wy = gy - y0f;
            int y0 = (int)y0f;
            float vy0 = (y0 >= 0 && y0 <= 62) ? 1.f : 0.f;
            float vy1 = (y0 >= -1 && y0 <= 61) ? 1.f : 0.f;
            int yc0 = min(max(y0, 0), 62);
            int yc1 = min(max(y0 + 1, 0), 62);
            const float* T0 = T + yc0*63;
            const float* T1 = T + yc1*63;
            float w0y = (1.f - wy) * vy0;
            float w1y = wy * vy1;
            float Cx = fmaf(qx0 - p.x, 15.5f, 31.f);
            #pragma unroll
            for (int r = 0; r < 16; r++) {
                float gx = fmaf((float)r, 0.96875f, Cx);
                float x0f = floorf(gx);
                float wx = gx - x0f;
                int x0 = (int)x0f;
                float vx0 = (x0 >= 0 && x0 <= 62) ? 1.f : 0.f;
                float vx1 = (x0 >= -1 && x0 <= 61) ? 1.f : 0.f;
                int xc0 = min(max(x0, 0), 62);
                int xc1 = min(max(x0 + 1, 0), 62);
                float t00 = T0[xc0], t01 = T0[xc1];
                float t10 = T1[xc0], t11 = T1[xc1];
                float wx0 = (1.f - wx) * vx0, wx1 = wx * vx1;
                float bias = w0y * (wx0*t00 + wx1*t01) + w1y * (wx0*t10 + wx1*t11);
                acc[r][j] += bias;
            }
        }
    }

    // ---- softmax (warp shuffle + tiny smem combine)
    float rv[16];
    #pragma unroll
    for (int r = 0; r < 16; r++)
        rv[r] = fmaxf(fmaxf(acc[r][0], acc[r][1]), fmaxf(acc[r][2], acc[r][3]));
    #pragma unroll
    for (int off = 16; off >= 1; off >>= 1)
        #pragma unroll
        for (int r = 0; r < 16; r++)
            rv[r] = fmaxf(rv[r], __shfl_xor_sync(0xffffffffu, rv[r], off));
    if (lane == 0)
        #pragma unroll
        for (int r = 0; r < 16; r++) redw[r*8 + warp] = rv[r];
    __syncthreads();
    if (tid < 16) {
        float m = redw[tid*8];
        #pragma unroll
        for (int w = 1; w < 8; w++) m = fmaxf(m, redw[tid*8 + w]);
        fin[tid] = m;
    }
    __syncthreads();
    #pragma unroll
    for (int r = 0; r < 16; r++) {
        float m = fin[r];
        float s = 0.f;
        #pragma unroll
        for (int j = 0; j < 4; j++) { acc[r][j] = __expf(acc[r][j] - m); s += acc[r][j]; }
        rv[r] = s;
    }
    #pragma unroll
    for (int off = 16; off >= 1; off >>= 1)
        #pragma unroll
        for (int r = 0; r < 16; r++)
            rv[r] += __shfl_xor_sync(0xffffffffu, rv[r], off);
    if (lane == 0)
        #pragma unroll
        for (int r = 0; r < 16; r++) redw[r*8 + warp] = rv[r];
    __syncthreads();
    if (tid < 16) {
        float s = 0.f;
        #pragma unroll
        for (int w = 0; w < 8; w++) s += redw[tid*8 + w];
        fin[16 + tid] = 1.f / s;
    }

    // store exp'd p transposed: p_s[n][r], stride 20 (normalize folded into PV)
    #pragma unroll
    for (int j = 0; j < 4; j++) {
        int n = tid + 256*j;
        #pragma unroll
        for (int rq = 0; rq < 4; rq++) {
            float4 wv = make_float4(acc[rq*4+0][j], acc[rq*4+1][j],
                                    acc[rq*4+2][j], acc[rq*4+3][j]);
            *(float4*)&p_s[n*P_STRIDE + rq*4] = wv;
        }
    }
    __syncthreads();

    // ---- PV: out[c][m] = inv[m] * sum_n p[n][m] v[c][n]
    int combo = tid >> 3;          // 32 combos
    int split = tid & 7;           // 8-way n split (interleaved)
    int cq = (combo & 7) * 4;
    int rq = (combo >> 3) * 4;
    float o4[4][4] = {};           // [ri][ci]
    const float* vb = vg + (size_t)bh * 32768;

    int lc = tid & 31;             // loader channel
    int nb = (tid >> 5) * 16;      // loader n base
    #pragma unroll 1
    for (int chk = 0; chk < 8; chk++) {
        #pragma unroll
        for (int ii = 0; ii < 16; ii += 4) {
            float4 t = *(const float4*)(vb + lc*1024 + chk*128 + nb + ii);
            v_s[(nb+ii+0)*V_STRIDE + lc] = t.x;
            v_s[(nb+ii+1)*V_STRIDE + lc] = t.y;
            v_s[(nb+ii+2)*V_STRIDE + lc] = t.z;
            v_s[(nb+ii+3)*V_STRIDE + lc] = t.w;
        }
        __syncthreads();
        #pragma unroll
        for (int i = 0; i < 16; i++) {
            int nl = i*8 + split;
            float4 p4 = *(const float4*)&p_s[(chk*128 + nl)*P_STRIDE + rq];
            float4 v4 = *(const float4*)&v_s[nl*V_STRIDE + cq];
            o4[0][0] = fmaf(p4.x, v4.x, o4[0][0]); o4[0][1] = fmaf(p4.x, v4.y, o4[0][1]);
            o4[0][2] = fmaf(p4.x, v4.z, o4[0][2]); o4[0][3] = fmaf(p4.x, v4.w, o4[0][3]);
            o4[1][0] = fmaf(p4.y, v4.x, o4[1][0]); o4[1][1] = fmaf(p4.y, v4.y, o4[1][1]);
            o4[1][2] = fmaf(p4.y, v4.z, o4[1][2]); o4[1][3] = fmaf(p4.y, v4.w, o4[1][3]);
            o4[2][0] = fmaf(p4.z, v4.x, o4[2][0]); o4[2][1] = fmaf(p4.z, v4.y, o4[2][1]);
            o4[2][2] = fmaf(p4.z, v4.z, o4[2][2]); o4[2][3] = fmaf(p4.z, v4.w, o4[2][3]);
            o4[3][0] = fmaf(p4.w, v4.x, o4[3][0]); o4[3][1] = fmaf(p4.w, v4.y, o4[3][1]);
            o4[3][2] = fmaf(p4.w, v4.z, o4[3][2]); o4[3][3] = fmaf(p4.w, v4.w, o4[3][3]);
        }
        __syncthreads();
    }
    // reduce over the 8 splits (adjacent lanes)
    #pragma unroll
    for (int off = 4; off >= 1; off >>= 1)
        #pragma unroll
        for (int ri = 0; ri < 4; ri++)
            #pragma unroll
            for (int ci = 0; ci < 4; ci++)
                o4[ri][ci] += __shfl_xor_sync(0xffffffffu, o4[ri][ci], off);
    if (split == 0) {
        #pragma unroll
        for (int ri = 0; ri < 4; ri++) {
            float inv = fin[16 + rq + ri];
            #pragma unroll
            for (int ci = 0; ci < 4; ci++)
                out[(size_t)(bh*32 + cq + ci)*1024 + m0 + rq + ri] = o4[ri][ci] * inv;
        }
    }
}

// ---------------- launch ----------------
extern "C" void kernel_launch(void* const* d_in, const int* in_sizes, int n_in,
                              void* d_out, int out_size)
{
    const float* x    = (const float*)d_in[0];
    const float* Wq   = (const float*)d_in[1];
    const float* bq   = (const float*)d_in[2];
    const float* Wk   = (const float*)d_in[3];
    const float* bk   = (const float*)d_in[4];
    const float* Wv   = (const float*)d_in[5];
    const float* bv   = (const float*)d_in[6];
    const float* Wo   = (const float*)d_in[7];
    const float* bo   = (const float*)d_in[8];
    const float* dw_w = (const float*)d_in[9];
    const float* dw_b = (const float*)d_in[10];
    const float* ln_g = (const float*)d_in[11];
    const float* ln_b = (const float*)d_in[12];
    const float* pw_w = (const float*)d_in[13];
    const float* rpe  = (const float*)d_in[14];

    float *q, *xs, *k, *v, *ob;
    float2* pos;
    cudaGetSymbolAddress((void**)&q,   g_q);
    cudaGetSymbolAddress((void**)&xs,  g_xs);
    cudaGetSymbolAddress((void**)&k,   g_k);
    cudaGetSymbolAddress((void**)&v,   g_v);
    cudaGetSymbolAddress((void**)&ob,  g_o);
    cudaGetSymbolAddress((void**)&pos, g_pos);

    gemm384<<<dim3(16, 6, 2), 256>>>(Wq, bq, x, q);
    dwconv_kernel<<<BG * 64, 256>>>(q, dw_w, dw_b, k);   // k buffer as tmp
    offs_kernel<<<BG * 8, 256>>>(k, ln_g, ln_b, pw_w, pos);
    sample_kernel<<<3072, 256>>>(x, pos, xs);
    gemm384_kv<<<dim3(16, 12, 2), 256>>>(Wk, bk, Wv, bv, xs, k, v);

    const int SMEM = (20480 + 4608 + 512 + 128 + 32) * 4;  // 103040 B
    cudaFuncSetAttribute(attn_kernel, cudaFuncAttributeMaxDynamicSharedMemorySize, SMEM);
    attn_kernel<<<dim3(64, 24), 256, SMEM>>>(q, k, v, pos, rpe, ob);

    gemm384<<<dim3(16, 6, 2), 256>>>(Wo, bo, ob, (float*)d_out);
}